// round 1
// baseline (speedup 1.0000x reference)
#include <cuda_runtime.h>

// LinearAttention fused pipeline, fp32 with f32x2 packed FMA.
// Stages:
//  k1: per (b, 128-pos chunk): kv = W_kv @ x, softmax(k) per head, accumulate
//      partial context outer-products -> g_ctx_partial
//  k2: reduce context partials per b; fold W_out through ctx into M[64][128]
//  k3: per (b, 64-pos chunk): q = softmax(W_q @ x)*scale; pre-BN out = M @ q + b_out;
//      write pre-BN + deterministic per-block channel sum/sumsq partials
//  k4: finalize BN stats -> per-channel scale/shift
//  k5: elementwise affine -> final output

#define HW 16384

__device__ float g_ctx_partial[16 * 128 * 4096];   // 32 MB
__device__ float g_M[16 * 64 * 128];               // 512 KB
__device__ float g_prebn[16 * 64 * 16384];         // 64 MB
__device__ float g_stats_partial[4096 * 128];      // 2 MB
__device__ float g_scale[64];
__device__ float g_shift[64];

__device__ __forceinline__ unsigned long long pack2(float v) {
    unsigned long long r;
    asm("mov.b64 %0, {%1, %1};" : "=l"(r) : "f"(v));
    return r;
}
__device__ __forceinline__ void ffma2(unsigned long long& d,
                                      unsigned long long a,
                                      unsigned long long b) {
    asm("fma.rn.f32x2 %0, %1, %2, %0;" : "+l"(d) : "l"(a), "l"(b));
}
__device__ __forceinline__ float2 unpack2(unsigned long long v) {
    float2 f;
    asm("mov.b64 {%0, %1}, %2;" : "=f"(f.x), "=f"(f.y) : "l"(v));
    return f;
}

// ---------------------------------------------------------------------------
// Kernel 1: context partials. 256 threads, P=128 positions per block.
// smem: Wkv[256][65] (k,v rows of w_qkv) + x tile [64][128] + kv staging [8][256]
// ---------------------------------------------------------------------------
__global__ void __launch_bounds__(256) k1_ctx(const float* __restrict__ x,
                                              const float* __restrict__ w_qkv) {
    extern __shared__ float sm[];
    float* Wsm = sm;                   // 256*65 = 16640
    float* xs  = sm + 256 * 65;        // 64*128 = 8192
    float* kvs = sm + 256 * 65 + 64 * 128;  // 8*256 = 2048
    const int t = threadIdx.x;
    const int b = blockIdx.y, chunk = blockIdx.x;

    // w_qkv rows 128..383 = k then v
    for (int i = t; i < 256 * 64; i += 256) {
        int r = i >> 6, c = i & 63;
        Wsm[r * 65 + c] = w_qkv[128 * 64 + i];
    }
    const float* xb = x + ((size_t)b * 64) * HW + chunk * 128;
    for (int i = t; i < 64 * 128; i += 256) {
        int c = i >> 7, p = i & 127;
        xs[i] = xb[(size_t)c * HW + p];
    }
    __syncthreads();

    const int hd = t & 127;            // thread's (h,d) for ctx accumulation
    const int h = hd >> 5;
    const int d = hd & 31;
    const int e0 = (t >> 7) << 4;      // 16 e's per thread
    const int vbase = 128 + h * 32 + e0;

    unsigned long long ctx2[8];
#pragma unroll
    for (int i = 0; i < 8; i++) ctx2[i] = 0ull;

    const float* wrow = Wsm + t * 65;
    const bool is_k = (t < 128);       // warps 0-3 hold k channels, lane == d

    for (int g = 0; g < 8; g++) {      // 8 groups of 16 positions
        unsigned long long acc2[8];
#pragma unroll
        for (int i = 0; i < 8; i++) acc2[i] = 0ull;
#pragma unroll
        for (int c = 0; c < 64; c++) {
            unsigned long long w2 = pack2(wrow[c]);
            const ulonglong2* xp = (const ulonglong2*)(xs + c * 128 + g * 16);
#pragma unroll
            for (int q = 0; q < 4; q++) {
                ulonglong2 xv = xp[q];
                ffma2(acc2[2 * q], w2, xv.x);
                ffma2(acc2[2 * q + 1], w2, xv.y);
            }
        }
        float a[16];
#pragma unroll
        for (int i = 0; i < 8; i++) {
            float2 f = unpack2(acc2[i]);
            a[2 * i] = f.x; a[2 * i + 1] = f.y;
        }
        if (is_k) {
            // softmax over d (32 lanes of the warp) per position
#pragma unroll
            for (int j = 0; j < 16; j++) {
                float v = a[j];
                float m = v;
#pragma unroll
                for (int o = 16; o > 0; o >>= 1)
                    m = fmaxf(m, __shfl_xor_sync(0xffffffffu, m, o));
                float e = __expf(v - m);
                float s = e;
#pragma unroll
                for (int o = 16; o > 0; o >>= 1)
                    s += __shfl_xor_sync(0xffffffffu, s, o);
                a[j] = e / s;
            }
        }
#pragma unroll
        for (int half = 0; half < 2; half++) {
#pragma unroll
            for (int j = 0; j < 8; j++) kvs[j * 256 + t] = a[half * 8 + j];
            __syncthreads();
#pragma unroll
            for (int j = 0; j < 8; j++) {
                unsigned long long k2 = pack2(kvs[j * 256 + hd]);
                const ulonglong2* vp = (const ulonglong2*)(kvs + j * 256 + vbase);
#pragma unroll
                for (int q = 0; q < 4; q++) {
                    ulonglong2 vv = vp[q];
                    ffma2(ctx2[2 * q], k2, vv.x);
                    ffma2(ctx2[2 * q + 1], k2, vv.y);
                }
            }
            __syncthreads();
        }
    }
    float* op = g_ctx_partial + ((size_t)(b * 128 + chunk)) * 4096 +
                h * 1024 + d * 32 + e0;
#pragma unroll
    for (int i = 0; i < 8; i++) {
        float2 f = unpack2(ctx2[i]);
        op[2 * i] = f.x;
        op[2 * i + 1] = f.y;
    }
}

// ---------------------------------------------------------------------------
// Kernel 2: reduce ctx partials per batch, compute M[c][h*32+d] =
//           sum_e w_out[c][h*32+e] * ctx[h][d][e]
// ---------------------------------------------------------------------------
__global__ void __launch_bounds__(256) k2_reduce_M(const float* __restrict__ w_out) {
    __shared__ float ctx_sm[4096];
    const int b = blockIdx.x, t = threadIdx.x;
    const float* p = g_ctx_partial + (size_t)b * 128 * 4096 + t;
    float acc[16];
#pragma unroll
    for (int j = 0; j < 16; j++) acc[j] = 0.f;
    for (int ch = 0; ch < 128; ch++) {
#pragma unroll
        for (int j = 0; j < 16; j++) acc[j] += p[(size_t)ch * 4096 + j * 256];
    }
#pragma unroll
    for (int j = 0; j < 16; j++) ctx_sm[t + j * 256] = acc[j];
    __syncthreads();
    for (int j = 0; j < 32; j++) {
        int flat = t + j * 256;
        int co = flat >> 7, hdx = flat & 127;
        int hh = hdx >> 5, dd = hdx & 31;
        const float* wo = w_out + co * 128 + hh * 32;
        const float* cc = ctx_sm + hh * 1024 + dd * 32;
        float s = 0.f;
#pragma unroll
        for (int e = 0; e < 32; e++) s += wo[e] * cc[e];
        g_M[(size_t)b * 8192 + flat] = s;
    }
}

// ---------------------------------------------------------------------------
// Kernel 3: q path + fused projection. 512 threads, P=64 positions per block.
// smem: WM (Wq then reused for M) + x tile + q staging (stride 68)
// ---------------------------------------------------------------------------
__global__ void __launch_bounds__(512) k3_apply(const float* __restrict__ x,
                                                const float* __restrict__ w_qkv,
                                                const float* __restrict__ b_out) {
    extern __shared__ float sm[];
    float* WM = sm;                         // max(128*65, 64*129) = 8320
    float* xs = sm + 8320;                  // 64*64 = 4096
    float* qs = sm + 8320 + 4096;           // 128*68 = 8704
    __shared__ float r1[512], r2[512];
    const int t = threadIdx.x;
    const int b = blockIdx.y, chunk = blockIdx.x;   // 256 chunks of 64 positions

    for (int i = t; i < 128 * 64; i += 512) {
        int r = i >> 6, c = i & 63;
        WM[r * 65 + c] = w_qkv[i];          // q rows 0..127
    }
    const float* xb = x + ((size_t)b * 64) * HW + chunk * 64;
    for (int i = t; i < 64 * 64; i += 512) {
        int c = i >> 6, p = i & 63;
        xs[i] = xb[(size_t)c * HW + p];
    }
    __syncthreads();

    // q GEMM: channel = t&127, 16 positions starting at (t>>7)*16
    const int ch = t & 127;
    const int p0q = (t >> 7) << 4;
    {
        unsigned long long acc2[8];
#pragma unroll
        for (int i = 0; i < 8; i++) acc2[i] = 0ull;
        const float* wrow = WM + ch * 65;
#pragma unroll
        for (int c = 0; c < 64; c++) {
            unsigned long long w2 = pack2(wrow[c]);
            const ulonglong2* xp = (const ulonglong2*)(xs + c * 64 + p0q);
#pragma unroll
            for (int q = 0; q < 4; q++) {
                ulonglong2 xv = xp[q];
                ffma2(acc2[2 * q], w2, xv.x);
                ffma2(acc2[2 * q + 1], w2, xv.y);
            }
        }
        float a[16];
#pragma unroll
        for (int i = 0; i < 8; i++) {
            float2 f = unpack2(acc2[i]);
            a[2 * i] = f.x; a[2 * i + 1] = f.y;
        }
        const float scale = 0.17677669529663687f;  // 32^-0.5
#pragma unroll
        for (int j = 0; j < 16; j++) {
            float v = a[j];
            float m = v;
#pragma unroll
            for (int o = 16; o > 0; o >>= 1)
                m = fmaxf(m, __shfl_xor_sync(0xffffffffu, m, o));
            float e = __expf(v - m);
            float s = e;
#pragma unroll
            for (int o = 16; o > 0; o >>= 1)
                s += __shfl_xor_sync(0xffffffffu, s, o);
            a[j] = e / s * scale;
        }
#pragma unroll
        for (int j = 0; j < 16; j++) qs[ch * 68 + p0q + j] = a[j];
    }
    __syncthreads();
    // load per-batch M over Wq's smem
    for (int i = t; i < 64 * 128; i += 512) {
        int co2 = i >> 7, hdx = i & 127;
        WM[co2 * 129 + hdx] = g_M[(size_t)b * 8192 + i];
    }
    __syncthreads();
    // out GEMM: out_pre[co][p] = sum_hd M[co][hd] * q[hd][p] + b_out[co]
    const int co = t & 63;
    const int p0 = (t >> 6) << 3;
    unsigned long long acc2[4];
#pragma unroll
    for (int i = 0; i < 4; i++) acc2[i] = 0ull;
    const float* mrow = WM + co * 129;
#pragma unroll
    for (int hdx = 0; hdx < 128; hdx++) {
        unsigned long long m2 = pack2(mrow[hdx]);
        const ulonglong2* qp = (const ulonglong2*)(qs + hdx * 68 + p0);
        ulonglong2 q0 = qp[0], q1 = qp[1];
        ffma2(acc2[0], m2, q0.x);
        ffma2(acc2[1], m2, q0.y);
        ffma2(acc2[2], m2, q1.x);
        ffma2(acc2[3], m2, q1.y);
    }
    float ov[8];
#pragma unroll
    for (int i = 0; i < 4; i++) {
        float2 f = unpack2(acc2[i]);
        ov[2 * i] = f.x; ov[2 * i + 1] = f.y;
    }
    float bo = __ldg(b_out + co);
    float s1 = 0.f, s2 = 0.f;
#pragma unroll
    for (int i = 0; i < 8; i++) {
        ov[i] += bo;
        s1 += ov[i];
        s2 += ov[i] * ov[i];
    }
    float* op = g_prebn + ((size_t)(b * 64 + co)) * HW + chunk * 64 + p0;
    *(float4*)op = make_float4(ov[0], ov[1], ov[2], ov[3]);
    *(float4*)(op + 4) = make_float4(ov[4], ov[5], ov[6], ov[7]);
    // deterministic per-block channel stats
    r1[t] = s1; r2[t] = s2;
    __syncthreads();
    if (t < 64) {
        float S1 = 0.f, S2 = 0.f;
#pragma unroll
        for (int q = 0; q < 8; q++) {
            S1 += r1[t + 64 * q];
            S2 += r2[t + 64 * q];
        }
        int blk = b * 256 + chunk;
        g_stats_partial[blk * 128 + t] = S1;
        g_stats_partial[blk * 128 + 64 + t] = S2;
    }
}

// ---------------------------------------------------------------------------
// Kernel 4: finalize BN stats. One block per channel.
// ---------------------------------------------------------------------------
__global__ void __launch_bounds__(256) k4_stats(const float* __restrict__ gamma,
                                                const float* __restrict__ beta) {
    __shared__ float a1[256], a2[256];
    const int c = blockIdx.x, t = threadIdx.x;
    float s1 = 0.f, s2 = 0.f;
    for (int blk = t; blk < 4096; blk += 256) {
        s1 += g_stats_partial[blk * 128 + c];
        s2 += g_stats_partial[blk * 128 + 64 + c];
    }
    a1[t] = s1; a2[t] = s2;
    __syncthreads();
    for (int o = 128; o > 0; o >>= 1) {
        if (t < o) { a1[t] += a1[t + o]; a2[t] += a2[t + o]; }
        __syncthreads();
    }
    if (t == 0) {
        const float invN = 1.0f / 262144.0f;   // B*H*W
        float mean = a1[0] * invN;
        float var = a2[0] * invN - mean * mean;
        float sc = gamma[c] * rsqrtf(var + 1e-5f);
        g_scale[c] = sc;
        g_shift[c] = beta[c] - mean * sc;
    }
}

// ---------------------------------------------------------------------------
// Kernel 5: elementwise BN affine
// ---------------------------------------------------------------------------
__global__ void __launch_bounds__(256) k5_affine(float* __restrict__ out) {
    int i4 = blockIdx.x * 256 + threadIdx.x;   // float4 index, 4194304 total
    int c = (i4 >> 12) & 63;                   // 4096 float4 per (b,c) row
    float4 v = ((const float4*)g_prebn)[i4];
    float s = g_scale[c], sh = g_shift[c];
    v.x = fmaf(v.x, s, sh);
    v.y = fmaf(v.y, s, sh);
    v.z = fmaf(v.z, s, sh);
    v.w = fmaf(v.w, s, sh);
    ((float4*)out)[i4] = v;
}

extern "C" void kernel_launch(void* const* d_in, const int* in_sizes, int n_in,
                              void* d_out, int out_size) {
    const float* x     = (const float*)d_in[0];
    const float* w_qkv = (const float*)d_in[1];
    const float* w_out = (const float*)d_in[2];
    const float* b_out = (const float*)d_in[3];
    const float* gamma = (const float*)d_in[4];
    const float* beta  = (const float*)d_in[5];
    float* out = (float*)d_out;

    const int smem1 = (256 * 65 + 64 * 128 + 8 * 256) * 4;          // 107520
    const int smem3 = (8320 + 4096 + 8704) * 4;                      // 84480
    cudaFuncSetAttribute(k1_ctx, cudaFuncAttributeMaxDynamicSharedMemorySize, smem1);
    cudaFuncSetAttribute(k3_apply, cudaFuncAttributeMaxDynamicSharedMemorySize, smem3);

    k1_ctx<<<dim3(128, 16), 256, smem1>>>(x, w_qkv);
    k2_reduce_M<<<16, 256>>>(w_out);
    k3_apply<<<dim3(256, 16), 512, smem3>>>(x, w_qkv, b_out);
    k4_stats<<<64, 256>>>(gamma, beta);
    k5_affine<<<16384, 256>>>(out);
}